// round 15
// baseline (speedup 1.0000x reference)
#include <cuda_runtime.h>
#include <cuda_fp16.h>
#include <cstdint>

// ---------------- problem constants ----------------
#define NNODE 16000
#define NEDGE 128000
#define GATD 768          // GAT dim
#define XD 800            // meta-in dim (768 gat + 32 node)
#define XDP 832           // padded K for GEMM2 (13 x 64)
#define MD 128            // meta out dim
#define PD 384            // P1(dst part) | P2(src part) | Xself
#define SCAN_BLOCKS 63    // ceil(NNODE/256)

// ---------------- device scratch (no allocs allowed) ----------------
__device__ __half   g_hh[NNODE * GATD];      // h in fp16 (only consumer: gather)
__device__ float    g_P[NNODE * PD];         // 24.6 MB
__device__ float    g_asrc[NNODE];
__device__ float    g_adst[NNODE];
__device__ unsigned g_amax[NNODE];           // ordered-float bits (0 = -inf sentinel)
__device__ float    g_denom[NNODE];
__device__ float    g_alphaE[NEDGE];
__device__ int      g_deg[NNODE];
__device__ int      g_rowstart[NNODE];
__device__ int      g_pos[NNODE];
__device__ int      g_csr_src[NEDGE];
__device__ int      g_csr_eid[NEDGE];
__device__ float    g_csr_ex[NEDGE];
__device__ int      g_bsum[64];
__device__ int      g_bofs[64];
// fp16 operands
__device__ __half g_A1[NNODE * GATD];
__device__ __half g_X[NNODE * XDP];
__device__ __half g_W1[GATD * GATD];   // W_gat^T  [n,k]
__device__ __half g_W2[PD * XDP];      // Wcat^T   [n,k]

// ---------------- helpers ----------------
__device__ __forceinline__ float lrelu(float x) { return x >= 0.f ? x : 0.2f * x; }
__device__ __forceinline__ unsigned f2o(float f) {
    unsigned b = __float_as_uint(f);
    return (b & 0x80000000u) ? ~b : (b | 0x80000000u);
}
__device__ __forceinline__ float o2f(unsigned b) {
    b = (b & 0x80000000u) ? (b & 0x7fffffffu) : ~b;
    return __uint_as_float(b);
}
__device__ __forceinline__ uint32_t smem_u32(const void* p) {
    uint32_t a;
    asm("{ .reg .u64 t; cvta.to.shared.u64 t, %1; cvt.u32.u64 %0, t; }" : "=r"(a) : "l"(p));
    return a;
}
__device__ __forceinline__ void ldm_x4(uint32_t& r0, uint32_t& r1, uint32_t& r2, uint32_t& r3,
                                       uint32_t addr) {
    asm volatile("ldmatrix.sync.aligned.m8n8.x4.shared.b16 {%0,%1,%2,%3}, [%4];"
                 : "=r"(r0), "=r"(r1), "=r"(r2), "=r"(r3) : "r"(addr));
}
__device__ __forceinline__ void mma16816(float* c, const uint32_t* a, uint32_t b0, uint32_t b1) {
    asm volatile(
        "mma.sync.aligned.m16n8k16.row.col.f32.f16.f16.f32 "
        "{%0,%1,%2,%3}, {%4,%5,%6,%7}, {%8,%9}, {%0,%1,%2,%3};"
        : "+f"(c[0]), "+f"(c[1]), "+f"(c[2]), "+f"(c[3])
        : "r"(a[0]), "r"(a[1]), "r"(a[2]), "r"(a[3]), "r"(b0), "r"(b1));
}
__device__ __forceinline__ void cp16(uint32_t dst, const void* src) {
    asm volatile("cp.async.cg.shared.global [%0], [%1], 16;" :: "r"(dst), "l"(src));
}
#define CP_COMMIT() asm volatile("cp.async.commit_group;" ::: "memory")
#define CP_WAIT2()  asm volatile("cp.async.wait_group 2;" ::: "memory")
#define CP_WAIT1()  asm volatile("cp.async.wait_group 1;" ::: "memory")
#define CP_WAIT0()  asm volatile("cp.async.wait_group 0;" ::: "memory")

__device__ __forceinline__ void unpack8(uint4 v, float* f) {
    float2 a = __half22float2(*(__half2*)&v.x);
    float2 b = __half22float2(*(__half2*)&v.y);
    float2 c = __half22float2(*(__half2*)&v.z);
    float2 d = __half22float2(*(__half2*)&v.w);
    f[0] = a.x; f[1] = a.y; f[2] = b.x; f[3] = b.y;
    f[4] = c.x; f[5] = c.y; f[6] = d.x; f[7] = d.y;
}
__device__ __forceinline__ uint4 pack8(const float* f) {
    uint4 o;
    __half2 h0 = __floats2half2_rn(f[0], f[1]);
    __half2 h1 = __floats2half2_rn(f[2], f[3]);
    __half2 h2 = __floats2half2_rn(f[4], f[5]);
    __half2 h3 = __floats2half2_rn(f[6], f[7]);
    o.x = *(uint32_t*)&h0; o.y = *(uint32_t*)&h1;
    o.z = *(uint32_t*)&h2; o.w = *(uint32_t*)&h3;
    return o;
}

// ---------------- fused prep kernel (block-range dispatch) ----------------
#define PREP_B_A1  6000     // cvtA1: NNODE*GATD/4 float4, 2 per thread
#define PREP_B_NL  2000     // nodeL: NNODE*32 / 256
#define PREP_B_W2  1248     // cvtW2: PD*XDP / 256
#define PREP_B_W1  576      // cvtW1: (768/32)^2 tiles
#define PREP_B_Z   63       // zero init: ceil(16000/256)
#define PREP_BLOCKS (PREP_B_A1 + PREP_B_NL + PREP_B_W2 + PREP_B_W1 + PREP_B_Z)

__global__ void k_prep(const float* __restrict__ mf, const float* __restrict__ nf,
                       const float* __restrict__ Wnode, const float* __restrict__ bnode,
                       const float* __restrict__ Wg,
                       const float* __restrict__ Wnbr, const float* __restrict__ Wself) {
    __shared__ float tile[32][33];
    int b = blockIdx.x;
    int t = threadIdx.x;
    if (b < PREP_B_A1) {                       // A1 convert (2x float4 -> 2x half2x2)
        int idx0 = b * 512 + t;
#pragma unroll
        for (int u = 0; u < 2; u++) {
            int idx = idx0 + u * 256;
            float4 v = ((const float4*)mf)[idx];
            __half2 h0 = __floats2half2_rn(v.x, v.y);
            __half2 h1 = __floats2half2_rn(v.z, v.w);
            uint2 o;
            o.x = *(uint32_t*)&h0;
            o.y = *(uint32_t*)&h1;
            ((uint2*)g_A1)[idx] = o;
        }
        return;
    }
    b -= PREP_B_A1;
    if (b < PREP_B_NL) {                       // node learner -> X cols 768:832
        int idx = b * 256 + t;
        int i = idx >> 5, j = idx & 31;
        const float* r = nf + i * 32;
        float s = bnode[j];
#pragma unroll
        for (int k = 0; k < 32; k++) s += r[k] * Wnode[k * 32 + j];
        size_t base = (size_t)i * XDP;
        g_X[base + 768 + j] = __float2half_rn(s);
        g_X[base + 800 + j] = __float2half(0.f);
        return;
    }
    b -= PREP_B_NL;
    if (b < PREP_B_W2) {                       // W2 build
        int idx = b * 256 + t;
        int n = idx / XDP, k = idx % XDP;
        float v = 0.f;
        if (k < XD) {
            if (n < 128)      v = Wnbr[k * 128 + n];
            else if (n < 256) v = Wnbr[(800 + k) * 128 + (n - 128)];
            else              v = Wself[k * 128 + (n - 256)];
        }
        g_W2[idx] = __float2half_rn(v);
        return;
    }
    b -= PREP_B_W2;
    if (b < PREP_B_W1) {                       // W1 transpose (32x32 tile)
        int tx = t & 31, ty = t >> 5;          // 32 x 8
        int n0 = (b % 24) * 32, k0 = (b / 24) * 32;
#pragma unroll
        for (int i = 0; i < 4; i++)
            tile[ty + i * 8][tx] = Wg[(size_t)(k0 + ty + i * 8) * GATD + n0 + tx];
        __syncthreads();
#pragma unroll
        for (int i = 0; i < 4; i++) {
            size_t o = (size_t)(n0 + ty + i * 8) * GATD + k0 + tx;
            g_W1[o] = __float2half_rn(tile[tx][ty + i * 8]);
        }
        return;
    }
    b -= PREP_B_W1;
    {                                          // zero init
        int i = b * 256 + t;
        if (i < NNODE) {
            g_asrc[i] = 0.f;
            g_adst[i] = 0.f;
            g_amax[i] = 0u;    // below every ordered-float
            g_deg[i] = 0;
        }
    }
}

// ---------------- warp-MMA fp16 GEMM (cp.async, templated chunk/stages) ----------------
// C[M,CN] = A @ B^T.  Block tile 128x128, 8 warps (2x4).
template <int CN, int KPAD, int NCH, int CHK, int NSTAGE, bool DO_ATT, bool HALF_OUT>
__device__ __forceinline__ void mma_gemm_body(const __half* __restrict__ A,
                                              const __half* __restrict__ B,
                                              float* __restrict__ Cf,
                                              __half* __restrict__ Ch,
                                              const float* __restrict__ att_s,
                                              const float* __restrict__ att_d) {
    constexpr int AS = CHK + 8;                 // smem row stride (halfs), (AS*2/16) odd
    constexpr int TB = 128 * AS * 2;            // tile bytes
    constexpr int STG = 2 * TB;                 // stage bytes (A|B)
    constexpr int SEG = CHK / 8;                // 16B segs per row
    constexpr int ITER = CHK / 16;              // copy iters per tile per thread

    extern __shared__ char smem[];
    const uint32_t sb = smem_u32(smem);

    const int t = threadIdx.x;
    const int lane = t & 31;
    const int wid = t >> 5;
    const int m0 = (wid >> 2) * 64;
    const int n0 = (wid & 3) * 32;
    const int bm = blockIdx.y * 128;
    const int bn = blockIdx.x * 128;

    const uint32_t aoff = (uint32_t)(((lane & 15) * AS + (lane >> 4) * 8) * 2);
    const uint32_t boff = (uint32_t)((((lane & 7) + ((lane >> 4) << 3)) * AS +
                                     (((lane >> 3) & 1) << 3)) * 2);

    float acc[4][4][4];
#pragma unroll
    for (int i = 0; i < 4; i++)
#pragma unroll
        for (int j = 0; j < 4; j++)
#pragma unroll
            for (int q = 0; q < 4; q++) acc[i][j][q] = 0.f;

    auto issue_chunk = [&](int c, int s) {
        const int c0 = c * CHK;
        const uint32_t dst = sb + (uint32_t)s * STG;
#pragma unroll
        for (int it = 0; it < ITER; it++) {
            int idx = it * 256 + t;
            int r = idx / SEG, j = idx % SEG;
            size_t ga = (size_t)(bm + r) * KPAD + c0 + j * 8;
            size_t gb = (size_t)(bn + r) * KPAD + c0 + j * 8;
            uint32_t doff = (uint32_t)((r * AS + j * 8) * 2);
            cp16(dst + doff, A + ga);
            cp16(dst + TB + doff, B + gb);
        }
    };

#pragma unroll
    for (int s = 0; s < NSTAGE - 1; s++) {
        issue_chunk(s, s);
        CP_COMMIT();
    }

    for (int c = 0; c < NCH; c++) {
        const int s = c % NSTAGE;
        if (c + NSTAGE - 1 < NCH) {
            issue_chunk(c + NSTAGE - 1, (c + NSTAGE - 1) % NSTAGE);
            CP_COMMIT();
            if (NSTAGE == 3) { CP_WAIT2(); } else { CP_WAIT1(); }
        } else {
            int pend = NCH - 1 - c;
            if (pend >= 2)      { CP_WAIT2(); }
            else if (pend == 1) { CP_WAIT1(); }
            else                { CP_WAIT0(); }
        }
        __syncthreads();

        const uint32_t baseA = sb + (uint32_t)s * STG;
        const uint32_t baseB = baseA + TB;

#pragma unroll
        for (int ks = 0; ks < CHK / 16; ks++) {
            const uint32_t kb = (uint32_t)(ks * 16 * 2);
            uint32_t bh[2][4];
#pragma unroll
            for (int p = 0; p < 2; p++) {
                uint32_t off = boff + (uint32_t)((n0 + p * 16) * AS * 2) + kb;
                ldm_x4(bh[p][0], bh[p][1], bh[p][2], bh[p][3], baseB + off);
            }
#pragma unroll
            for (int tm = 0; tm < 4; tm++) {
                uint32_t off = aoff + (uint32_t)((m0 + tm * 16) * AS * 2) + kb;
                uint32_t ah[4];
                ldm_x4(ah[0], ah[1], ah[2], ah[3], baseA + off);
#pragma unroll
                for (int tn = 0; tn < 4; tn++) {
                    int p = tn >> 1, q = tn & 1;
                    mma16816(acc[tm][tn], ah, bh[p][q * 2], bh[p][q * 2 + 1]);
                }
            }
        }
        __syncthreads();
    }

    const int rit = lane >> 2;
    const int cq = (lane & 3) * 2;
#pragma unroll
    for (int tm = 0; tm < 4; tm++) {
        float s1a = 0.f, s2a = 0.f, s1b = 0.f, s2b = 0.f;
#pragma unroll
        for (int tn = 0; tn < 4; tn++) {
            size_t row = (size_t)(bm + m0 + tm * 16 + rit);
            int col = bn + n0 + tn * 8 + cq;
            if (HALF_OUT) {
                __half2 v0 = __floats2half2_rn(acc[tm][tn][0], acc[tm][tn][1]);
                __half2 v1 = __floats2half2_rn(acc[tm][tn][2], acc[tm][tn][3]);
                *(__half2*)&Ch[row * CN + col] = v0;
                *(__half2*)&Ch[(row + 8) * CN + col] = v1;
            } else {
                *(float2*)&Cf[row * CN + col] = make_float2(acc[tm][tn][0], acc[tm][tn][1]);
                *(float2*)&Cf[(row + 8) * CN + col] = make_float2(acc[tm][tn][2], acc[tm][tn][3]);
            }
            if (DO_ATT) {
                float a0 = __ldg(att_s + col), a1 = __ldg(att_s + col + 1);
                float d0 = __ldg(att_d + col), d1 = __ldg(att_d + col + 1);
                s1a += acc[tm][tn][0] * a0 + acc[tm][tn][1] * a1;
                s2a += acc[tm][tn][0] * d0 + acc[tm][tn][1] * d1;
                s1b += acc[tm][tn][2] * a0 + acc[tm][tn][3] * a1;
                s2b += acc[tm][tn][2] * d0 + acc[tm][tn][3] * d1;
            }
        }
        if (DO_ATT) {
#pragma unroll
            for (int off = 1; off < 4; off <<= 1) {
                s1a += __shfl_xor_sync(0xffffffffu, s1a, off);
                s2a += __shfl_xor_sync(0xffffffffu, s2a, off);
                s1b += __shfl_xor_sync(0xffffffffu, s1b, off);
                s2b += __shfl_xor_sync(0xffffffffu, s2b, off);
            }
            if ((lane & 3) == 0) {
                int rowA = bm + m0 + tm * 16 + rit;
                atomicAdd(&g_asrc[rowA], s1a);
                atomicAdd(&g_adst[rowA], s2a);
                atomicAdd(&g_asrc[rowA + 8], s1b);
                atomicAdd(&g_adst[rowA + 8], s2b);
            }
        }
    }
}

// gemm1: K chunk 96, 2 stages (768 = 8x96); smem 2*2*128*104*2 = 106496
__global__ void __launch_bounds__(256, 2) k_gemm1(const float* __restrict__ att_s,
                                                  const float* __restrict__ att_d) {
    mma_gemm_body<GATD, GATD, 8, 96, 2, true, true>(g_A1, g_W1, nullptr, g_hh, att_s, att_d);
}
// gemm2: K chunk 64, 3 stages (832 = 13x64); smem 3*2*128*72*2 = 110592
__global__ void __launch_bounds__(256, 2) k_gemm2() {
    mma_gemm_body<PD, XDP, 13, 64, 3, false, false>(g_X, g_W2, g_P, nullptr, nullptr, nullptr);
}
#define GEMM1_SMEM (2 * 2 * 128 * 104 * 2)
#define GEMM2_SMEM (3 * 2 * 128 * 72 * 2)

// ---------------- edge alpha pass (deg + amax) ----------------
__global__ void k_edge_alpha(const int* __restrict__ ei) {
    int e = blockIdx.x * blockDim.x + threadIdx.x;
    if (e >= NEDGE) return;
    int s = ei[e], d = ei[NEDGE + e];
    float al = lrelu(g_asrc[s] + g_adst[d]);
    g_alphaE[e] = al;
    atomicMax(&g_amax[d], f2o(al));
    atomicAdd(&g_deg[d], 1);
}

// ---- scan stage 1: per-block inclusive scan of deg + block sums; phase2 amax/denom ----
__global__ void k_scan1() {
    __shared__ int wsum[8];
    int t = threadIdx.x, lane = t & 31, wid = t >> 5;
    int i = blockIdx.x * 256 + t;
    int v = (i < NNODE) ? g_deg[i] : 0;
    int incl = v;
#pragma unroll
    for (int o = 1; o < 32; o <<= 1) {
        int n = __shfl_up_sync(0xffffffffu, incl, o);
        if (lane >= o) incl += n;
    }
    if (lane == 31) wsum[wid] = incl;
    __syncthreads();
    if (wid == 0 && lane < 8) {
        int w = wsum[lane];
        int ws = w;
#pragma unroll
        for (int o = 1; o < 8; o <<= 1) {
            int n = __shfl_up_sync(0xffu, ws, o);
            if (lane >= o) ws += n;
        }
        wsum[lane] = ws - w;   // exclusive across warps
    }
    __syncthreads();
    incl += wsum[wid];
    if (i < NNODE) g_rowstart[i] = incl;               // temp: block-local inclusive
    if (t == 255) g_bsum[blockIdx.x] = incl;
    // phase 2: amax includes self; denom = exp(self - amax)
    if (i < NNODE) {
        float al = lrelu(g_asrc[i] + g_adst[i]);
        float am = fmaxf(o2f(g_amax[i]), al);          // o2f(0)=NaN -> returns al
        g_amax[i] = f2o(am);
        g_denom[i] = __expf(al - am);
    }
}

// ---- scan stage 2: exclusive scan of 63 block sums (one warp, 2 elems/lane) ----
__global__ void k_scan2() {
    int lane = threadIdx.x;
    int v0 = (2 * lane     < SCAN_BLOCKS) ? g_bsum[2 * lane]     : 0;
    int v1 = (2 * lane + 1 < SCAN_BLOCKS) ? g_bsum[2 * lane + 1] : 0;
    int p = v0 + v1;
    int incl = p;
#pragma unroll
    for (int o = 1; o < 32; o <<= 1) {
        int n = __shfl_up_sync(0xffffffffu, incl, o);
        if (lane >= o) incl += n;
    }
    int excl = incl - p;
    if (2 * lane < SCAN_BLOCKS)     g_bofs[2 * lane] = excl;
    if (2 * lane + 1 < SCAN_BLOCKS) g_bofs[2 * lane + 1] = excl + v0;
}

// ---- scan stage 3: finalize rowstart/pos ----
__global__ void k_scan3() {
    int i = blockIdx.x * 256 + threadIdx.x;
    if (i >= NNODE) return;
    int excl = g_bofs[blockIdx.x] + g_rowstart[i] - g_deg[i];
    g_rowstart[i] = excl;
    g_pos[i] = excl;
}

// fused CSR fill + exp + denom accumulate
__global__ void k_edge_build(const int* __restrict__ ei) {
    int e = blockIdx.x * blockDim.x + threadIdx.x;
    if (e >= NEDGE) return;
    int s = ei[e], d = ei[NEDGE + e];
    int p = atomicAdd(&g_pos[d], 1);
    g_csr_src[p] = s;
    g_csr_eid[p] = e;
    float ex = __expf(g_alphaE[e] - o2f(g_amax[d]));
    g_csr_ex[p] = ex;
    atomicAdd(&g_denom[d], ex);
}

// ---------------- GAT gather-aggregation: warp per node (unroll-4 edges) ----------------
__global__ void k_gat_aggr(const float* __restrict__ b_gat) {
    int warp = (blockIdx.x * blockDim.x + threadIdx.x) >> 5;
    int lane = threadIdx.x & 31;
    if (warp >= NNODE) return;
    int i = warp;
    float amaxv = o2f(g_amax[i]);
    float als = lrelu(g_asrc[i] + g_adst[i]);
    float inv_den = 1.0f / g_denom[i];
    float cs = __expf(als - amaxv) * inv_den;

    const uint4* hrow = (const uint4*)(g_hh + (size_t)i * GATD);
    const float4* bg = (const float4*)b_gat;
    float acc[3][8];
#pragma unroll
    for (int t = 0; t < 3; t++) {
        float f[8];
        unpack8(hrow[lane + 32 * t], f);
        float4 b0 = bg[2 * (lane + 32 * t)];
        float4 b1 = bg[2 * (lane + 32 * t) + 1];
        acc[t][0] = cs * f[0] + b0.x; acc[t][1] = cs * f[1] + b0.y;
        acc[t][2] = cs * f[2] + b0.z; acc[t][3] = cs * f[3] + b0.w;
        acc[t][4] = cs * f[4] + b1.x; acc[t][5] = cs * f[5] + b1.y;
        acc[t][6] = cs * f[6] + b1.z; acc[t][7] = cs * f[7] + b1.w;
    }
    int rs = g_rowstart[i], d = g_deg[i];
    for (int base = 0; base < d; base += 32) {
        int cnt = min(32, d - base);
        int sj = 0;
        float cj = 0.f;
        if (lane < cnt) {
            sj = g_csr_src[rs + base + lane];
            cj = g_csr_ex[rs + base + lane] * inv_den;
        }
        int k = 0;
        for (; k + 3 < cnt; k += 4) {
            int ss[4];
            float cc[4];
#pragma unroll
            for (int u = 0; u < 4; u++) {
                ss[u] = __shfl_sync(0xffffffffu, sj, k + u);
                cc[u] = __shfl_sync(0xffffffffu, cj, k + u);
            }
            uint4 r[4][3];
#pragma unroll
            for (int u = 0; u < 4; u++) {
                const uint4* hp = (const uint4*)(g_hh + (size_t)ss[u] * GATD);
#pragma unroll
                for (int t = 0; t < 3; t++) r[u][t] = __ldg(&hp[lane + 32 * t]);
            }
#pragma unroll
            for (int u = 0; u < 4; u++)
#pragma unroll
                for (int t = 0; t < 3; t++) {
                    float f[8];
                    unpack8(r[u][t], f);
#pragma unroll
                    for (int q = 0; q < 8; q++) acc[t][q] += cc[u] * f[q];
                }
        }
        for (; k < cnt; k++) {
            int s0 = __shfl_sync(0xffffffffu, sj, k);
            float c0 = __shfl_sync(0xffffffffu, cj, k);
            const uint4* h0 = (const uint4*)(g_hh + (size_t)s0 * GATD);
#pragma unroll
            for (int t = 0; t < 3; t++) {
                float f0[8];
                unpack8(__ldg(&h0[lane + 32 * t]), f0);
#pragma unroll
                for (int q = 0; q < 8; q++) acc[t][q] += c0 * f0[q];
            }
        }
    }
    size_t xbase = (size_t)i * XDP;
#pragma unroll
    for (int t = 0; t < 3; t++) {
        *(uint4*)(g_X + xbase + 8 * (lane + 32 * t)) = pack8(acc[t]);
    }
}

// ---------------- final aggregation: per-lane ea accumulation + unroll-4 P2 gather ----------------
__global__ void k_meta(float* __restrict__ out, const float* __restrict__ b_nbr,
                       const float* __restrict__ b_self, const float* __restrict__ W_nbr,
                       const float* __restrict__ W_edge, const float* __restrict__ b_edge,
                       const float* __restrict__ edge_attr) {
    __shared__ float sWe[16 * 128];
    __shared__ float sWE[16 * 16];
    __shared__ float sBN[128];
    for (int t = threadIdx.x; t < 2048; t += blockDim.x)
        sWe[t] = W_nbr[1600 * 128 + t];
    for (int t = threadIdx.x; t < 256; t += blockDim.x)
        sWE[t] = W_edge[t];
    __syncthreads();
    if (threadIdx.x < 128) {
        int c = threadIdx.x;
        float s = b_nbr[c];
#pragma unroll
        for (int k = 0; k < 16; k++) s += b_edge[k] * sWe[k * 128 + c];
        sBN[c] = s;
    }
    __syncthreads();

    int warp = (blockIdx.x * blockDim.x + threadIdx.x) >> 5;
    int lane = threadIdx.x & 31;
    if (warp >= NNODE) return;
    int i = warp;
    const float4* Pr = (const float4*)(g_P + (size_t)i * PD);
    float4 p1 = Pr[lane];        // dst-part
    float4 xs = Pr[64 + lane];   // self-part
    float4 bs = ((const float4*)b_self)[lane];
    float4 bn4 = *(const float4*)&sBN[lane * 4];
    float degf = (float)g_deg[i];
    float4 acc;
    acc.x = xs.x + bs.x + degf * (p1.x + bn4.x);
    acc.y = xs.y + bs.y + degf * (p1.y + bn4.y);
    acc.z = xs.z + bs.z + degf * (p1.z + bn4.z);
    acc.w = xs.w + bs.w + degf * (p1.w + bn4.w);

    float eas[16];
#pragma unroll
    for (int k = 0; k < 16; k++) eas[k] = 0.f;

    int rs = g_rowstart[i], d = g_deg[i];
    for (int base = 0; base < d; base += 32) {
        int cnt = min(32, d - base);
        int sj = 0;
        if (lane < cnt) {
            sj = g_csr_src[rs + base + lane];
            int ej = g_csr_eid[rs + base + lane];
            const float4* ear = (const float4*)(edge_attr + (size_t)ej * 16);
            float4 e0 = __ldg(ear), e1 = __ldg(ear + 1), e2 = __ldg(ear + 2), e3 = __ldg(ear + 3);
            eas[0] += e0.x;  eas[1] += e0.y;  eas[2] += e0.z;  eas[3] += e0.w;
            eas[4] += e1.x;  eas[5] += e1.y;  eas[6] += e1.z;  eas[7] += e1.w;
            eas[8] += e2.x;  eas[9] += e2.y;  eas[10] += e2.z; eas[11] += e2.w;
            eas[12] += e3.x; eas[13] += e3.y; eas[14] += e3.z; eas[15] += e3.w;
        }
        int k = 0;
        for (; k + 3 < cnt; k += 4) {
            int ss[4];
#pragma unroll
            for (int u = 0; u < 4; u++) ss[u] = __shfl_sync(0xffffffffu, sj, k + u);
            float4 p2[4];
#pragma unroll
            for (int u = 0; u < 4; u++)
                p2[u] = __ldg(&((const float4*)(g_P + (size_t)ss[u] * PD))[32 + lane]);
#pragma unroll
            for (int u = 0; u < 4; u++) {
                acc.x += p2[u].x;
                acc.y += p2[u].y;
                acc.z += p2[u].z;
                acc.w += p2[u].w;
            }
        }
        for (; k < cnt; k++) {
            int s0 = __shfl_sync(0xffffffffu, sj, k);
            float4 p2 = __ldg(&((const float4*)(g_P + (size_t)s0 * PD))[32 + lane]);
            acc.x += p2.x;
            acc.y += p2.y;
            acc.z += p2.z;
            acc.w += p2.w;
        }
    }

    // reduce per-lane ea partials across the warp
#pragma unroll
    for (int o = 16; o > 0; o >>= 1)
#pragma unroll
        for (int kk = 0; kk < 16; kk++)
            eas[kk] += __shfl_xor_sync(0xffffffffu, eas[kk], o);

    float tv[16];
#pragma unroll
    for (int kk = 0; kk < 16; kk++) {
        float s = 0.f;
#pragma unroll
        for (int j = 0; j < 16; j++) s += eas[j] * sWE[j * 16 + kk];
        tv[kk] = s;
    }
    int col = lane * 4;
#pragma unroll
    for (int kk = 0; kk < 16; kk++) {
        float4 wv = *(const float4*)&sWe[kk * 128 + col];
        float ev = tv[kk];
        acc.x += ev * wv.x;
        acc.y += ev * wv.y;
        acc.z += ev * wv.z;
        acc.w += ev * wv.w;
    }
    ((float4*)(out + (size_t)i * MD))[lane] = acc;
}

// ---------------- launch ----------------
extern "C" void kernel_launch(void* const* d_in, const int* in_sizes, int n_in,
                              void* d_out, int out_size) {
    const float* node_feature    = (const float*)d_in[0];
    const float* edge_attr       = (const float*)d_in[1];
    const float* message_feature = (const float*)d_in[2];
    const int*   edge_index      = (const int*)d_in[3];
    const float* W_node = (const float*)d_in[4];
    const float* b_node = (const float*)d_in[5];
    const float* W_edge = (const float*)d_in[6];
    const float* b_edge = (const float*)d_in[7];
    const float* W_gat  = (const float*)d_in[8];
    const float* att_src = (const float*)d_in[9];
    const float* att_dst = (const float*)d_in[10];
    const float* b_gat  = (const float*)d_in[11];
    const float* W_nbr  = (const float*)d_in[12];
    const float* b_nbr  = (const float*)d_in[13];
    const float* W_self = (const float*)d_in[14];
    const float* b_self = (const float*)d_in[15];
    float* out = (float*)d_out;

    cudaFuncSetAttribute(k_gemm1, cudaFuncAttributeMaxDynamicSharedMemorySize, GEMM1_SMEM);
    cudaFuncSetAttribute(k_gemm2, cudaFuncAttributeMaxDynamicSharedMemorySize, GEMM2_SMEM);

    // fused prep (A1 convert | node learner | W2 | W1 transpose | zero init)
    k_prep<<<PREP_BLOCKS, 256>>>(message_feature, node_feature, W_node, b_node,
                                 W_gat, W_nbr, W_self);

    // h = mf @ W_gat  (fp16 out, + fused attention scalar partial dots)
    k_gemm1<<<dim3(GATD / 128, NNODE / 128), 256, GEMM1_SMEM>>>(att_src, att_dst);

    // softmax structure (parallel 3-stage scan)
    k_edge_alpha<<<(NEDGE + 255) / 256, 256>>>(edge_index);
    k_scan1<<<SCAN_BLOCKS, 256>>>();
    k_scan2<<<1, 32>>>();
    k_scan3<<<SCAN_BLOCKS, 256>>>();
    k_edge_build<<<(NEDGE + 255) / 256, 256>>>(edge_index);

    // GAT aggregation -> X cols 0:768 (fp16 h rows)
    k_gat_aggr<<<(NNODE * 32 + 255) / 256, 256>>>(b_gat);

    // P = x @ Wcat  (fp16)
    k_gemm2<<<dim3(PD / 128, NNODE / 128), 256, GEMM2_SMEM>>>();

    // final per-node aggregation (fused edge learner) -> out
    k_meta<<<(NNODE * 32 + 255) / 256, 256>>>(out, b_nbr, b_self, W_nbr,
                                              W_edge, b_edge, edge_attr);
}

// round 16
// speedup vs baseline: 1.4859x; 1.4859x over previous
#include <cuda_runtime.h>
#include <cuda_fp16.h>
#include <cstdint>

// ---------------- problem constants ----------------
#define NNODE 16000
#define NEDGE 128000
#define GATD 768          // GAT dim
#define XD 800            // meta-in dim (768 gat + 32 node)
#define XDP 832           // padded K for GEMM2 (13 x 64)
#define MD 128            // meta out dim
#define PD 384            // P1(dst part) | P2(src part) | Xself
#define SCAN_BLOCKS 63    // ceil(NNODE/256)

// ---------------- device scratch (no allocs allowed) ----------------
__device__ __half   g_hh[NNODE * GATD];      // h in fp16 (only consumer: gather)
__device__ float    g_P[NNODE * PD];         // 24.6 MB
__device__ float    g_asrc[NNODE];
__device__ float    g_adst[NNODE];
__device__ unsigned g_amax[NNODE];           // ordered-float bits (0 = -inf sentinel)
__device__ float    g_denom[NNODE];
__device__ float    g_alphaE[NEDGE];
__device__ int      g_deg[NNODE];
__device__ int      g_rowstart[NNODE];
__device__ int      g_pos[NNODE];
__device__ int      g_csr_src[NEDGE];
__device__ int      g_csr_eid[NEDGE];
__device__ float    g_csr_ex[NEDGE];
__device__ int      g_bsum[64];
__device__ int      g_bofs[64];
// fp16 operands
__device__ __half g_A1[NNODE * GATD];
__device__ __half g_X[NNODE * XDP];
__device__ __half g_W1[GATD * GATD];   // W_gat^T  [n,k]
__device__ __half g_W2[PD * XDP];      // Wcat^T   [n,k]

// ---------------- helpers ----------------
__device__ __forceinline__ float lrelu(float x) { return x >= 0.f ? x : 0.2f * x; }
__device__ __forceinline__ unsigned f2o(float f) {
    unsigned b = __float_as_uint(f);
    return (b & 0x80000000u) ? ~b : (b | 0x80000000u);
}
__device__ __forceinline__ float o2f(unsigned b) {
    b = (b & 0x80000000u) ? (b & 0x7fffffffu) : ~b;
    return __uint_as_float(b);
}
__device__ __forceinline__ uint32_t smem_u32(const void* p) {
    uint32_t a;
    asm("{ .reg .u64 t; cvta.to.shared.u64 t, %1; cvt.u32.u64 %0, t; }" : "=r"(a) : "l"(p));
    return a;
}
__device__ __forceinline__ void ldm_x4(uint32_t& r0, uint32_t& r1, uint32_t& r2, uint32_t& r3,
                                       uint32_t addr) {
    asm volatile("ldmatrix.sync.aligned.m8n8.x4.shared.b16 {%0,%1,%2,%3}, [%4];"
                 : "=r"(r0), "=r"(r1), "=r"(r2), "=r"(r3) : "r"(addr));
}
__device__ __forceinline__ void mma16816(float* c, const uint32_t* a, uint32_t b0, uint32_t b1) {
    asm volatile(
        "mma.sync.aligned.m16n8k16.row.col.f32.f16.f16.f32 "
        "{%0,%1,%2,%3}, {%4,%5,%6,%7}, {%8,%9}, {%0,%1,%2,%3};"
        : "+f"(c[0]), "+f"(c[1]), "+f"(c[2]), "+f"(c[3])
        : "r"(a[0]), "r"(a[1]), "r"(a[2]), "r"(a[3]), "r"(b0), "r"(b1));
}
__device__ __forceinline__ void cp16(uint32_t dst, const void* src) {
    asm volatile("cp.async.cg.shared.global [%0], [%1], 16;" :: "r"(dst), "l"(src));
}
#define CP_COMMIT() asm volatile("cp.async.commit_group;" ::: "memory")
#define CP_WAIT2()  asm volatile("cp.async.wait_group 2;" ::: "memory")
#define CP_WAIT1()  asm volatile("cp.async.wait_group 1;" ::: "memory")
#define CP_WAIT0()  asm volatile("cp.async.wait_group 0;" ::: "memory")

__device__ __forceinline__ void unpack8(uint4 v, float* f) {
    float2 a = __half22float2(*(__half2*)&v.x);
    float2 b = __half22float2(*(__half2*)&v.y);
    float2 c = __half22float2(*(__half2*)&v.z);
    float2 d = __half22float2(*(__half2*)&v.w);
    f[0] = a.x; f[1] = a.y; f[2] = b.x; f[3] = b.y;
    f[4] = c.x; f[5] = c.y; f[6] = d.x; f[7] = d.y;
}
__device__ __forceinline__ uint4 pack8(const float* f) {
    uint4 o;
    __half2 h0 = __floats2half2_rn(f[0], f[1]);
    __half2 h1 = __floats2half2_rn(f[2], f[3]);
    __half2 h2 = __floats2half2_rn(f[4], f[5]);
    __half2 h3 = __floats2half2_rn(f[6], f[7]);
    o.x = *(uint32_t*)&h0; o.y = *(uint32_t*)&h1;
    o.z = *(uint32_t*)&h2; o.w = *(uint32_t*)&h3;
    return o;
}

// ---------------- fused prep kernel (block-range dispatch) ----------------
#define PREP_B_A1  6000     // cvtA1: NNODE*GATD/4 float4, 2 per thread
#define PREP_B_NL  2000     // nodeL: NNODE*32 / 256
#define PREP_B_W2  1248     // cvtW2: PD*XDP / 256
#define PREP_B_W1  576      // cvtW1: (768/32)^2 tiles
#define PREP_B_Z   63       // zero init: ceil(16000/256)
#define PREP_BLOCKS (PREP_B_A1 + PREP_B_NL + PREP_B_W2 + PREP_B_W1 + PREP_B_Z)

__global__ void k_prep(const float* __restrict__ mf, const float* __restrict__ nf,
                       const float* __restrict__ Wnode, const float* __restrict__ bnode,
                       const float* __restrict__ Wg,
                       const float* __restrict__ Wnbr, const float* __restrict__ Wself) {
    __shared__ float tile[32][33];
    int b = blockIdx.x;
    int t = threadIdx.x;
    if (b < PREP_B_A1) {                       // A1 convert (2x float4 -> 2x half2x2)
        int idx0 = b * 512 + t;
#pragma unroll
        for (int u = 0; u < 2; u++) {
            int idx = idx0 + u * 256;
            float4 v = ((const float4*)mf)[idx];
            __half2 h0 = __floats2half2_rn(v.x, v.y);
            __half2 h1 = __floats2half2_rn(v.z, v.w);
            uint2 o;
            o.x = *(uint32_t*)&h0;
            o.y = *(uint32_t*)&h1;
            ((uint2*)g_A1)[idx] = o;
        }
        return;
    }
    b -= PREP_B_A1;
    if (b < PREP_B_NL) {                       // node learner -> X cols 768:832
        int idx = b * 256 + t;
        int i = idx >> 5, j = idx & 31;
        const float* r = nf + i * 32;
        float s = bnode[j];
#pragma unroll
        for (int k = 0; k < 32; k++) s += r[k] * Wnode[k * 32 + j];
        size_t base = (size_t)i * XDP;
        g_X[base + 768 + j] = __float2half_rn(s);
        g_X[base + 800 + j] = __float2half(0.f);
        return;
    }
    b -= PREP_B_NL;
    if (b < PREP_B_W2) {                       // W2 build
        int idx = b * 256 + t;
        int n = idx / XDP, k = idx % XDP;
        float v = 0.f;
        if (k < XD) {
            if (n < 128)      v = Wnbr[k * 128 + n];
            else if (n < 256) v = Wnbr[(800 + k) * 128 + (n - 128)];
            else              v = Wself[k * 128 + (n - 256)];
        }
        g_W2[idx] = __float2half_rn(v);
        return;
    }
    b -= PREP_B_W2;
    if (b < PREP_B_W1) {                       // W1 transpose (32x32 tile)
        int tx = t & 31, ty = t >> 5;          // 32 x 8
        int n0 = (b % 24) * 32, k0 = (b / 24) * 32;
#pragma unroll
        for (int i = 0; i < 4; i++)
            tile[ty + i * 8][tx] = Wg[(size_t)(k0 + ty + i * 8) * GATD + n0 + tx];
        __syncthreads();
#pragma unroll
        for (int i = 0; i < 4; i++) {
            size_t o = (size_t)(n0 + ty + i * 8) * GATD + k0 + tx;
            g_W1[o] = __float2half_rn(tile[tx][ty + i * 8]);
        }
        return;
    }
    b -= PREP_B_W1;
    {                                          // zero init
        int i = b * 256 + t;
        if (i < NNODE) {
            g_asrc[i] = 0.f;
            g_adst[i] = 0.f;
            g_amax[i] = 0u;    // below every ordered-float
            g_deg[i] = 0;
        }
    }
}

// ---------------- warp-MMA fp16 GEMM (cp.async 3-stage, K chunk 64) ----------------
// (R14 winning geometry — 110.6 KB smem, 2 blocks/SM)
#define ASTRIDE 72
#define TILE_BYTES 18432                  // 128*72*2
#define STAGE_BYTES (2 * TILE_BYTES)      // A|B

template <int CN, int KPAD, int NCH, bool DO_ATT, bool HALF_OUT>
__device__ __forceinline__ void mma_gemm_body(const __half* __restrict__ A,
                                              const __half* __restrict__ B,
                                              float* __restrict__ Cf,
                                              __half* __restrict__ Ch,
                                              const float* __restrict__ att_s,
                                              const float* __restrict__ att_d) {
    extern __shared__ char smem[];
    const uint32_t sb = smem_u32(smem);

    const int t = threadIdx.x;
    const int lane = t & 31;
    const int wid = t >> 5;
    const int m0 = (wid >> 2) * 64;
    const int n0 = (wid & 3) * 32;
    const int bm = blockIdx.y * 128;
    const int bn = blockIdx.x * 128;

    const uint32_t aoff = (uint32_t)(((lane & 15) * ASTRIDE + (lane >> 4) * 8) * 2);
    const uint32_t boff = (uint32_t)((((lane & 7) + ((lane >> 4) << 3)) * ASTRIDE +
                                     (((lane >> 3) & 1) << 3)) * 2);

    float acc[4][4][4];
#pragma unroll
    for (int i = 0; i < 4; i++)
#pragma unroll
        for (int j = 0; j < 4; j++)
#pragma unroll
            for (int q = 0; q < 4; q++) acc[i][j][q] = 0.f;

    auto issue_chunk = [&](int c, int s) {
        const int c0 = c * 64;
        const uint32_t dst = sb + (uint32_t)s * STAGE_BYTES;
#pragma unroll
        for (int it = 0; it < 4; it++) {
            int idx = it * 256 + t;
            int r = idx >> 3, j = idx & 7;
            size_t ga = (size_t)(bm + r) * KPAD + c0 + j * 8;
            size_t gb = (size_t)(bn + r) * KPAD + c0 + j * 8;
            uint32_t doff = (uint32_t)((r * ASTRIDE + j * 8) * 2);
            cp16(dst + doff, A + ga);
            cp16(dst + TILE_BYTES + doff, B + gb);
        }
    };

    issue_chunk(0, 0);
    CP_COMMIT();
    issue_chunk(1, 1);
    CP_COMMIT();

    for (int c = 0; c < NCH; c++) {
        const int s = c % 3;
        if (c + 2 < NCH) {
            issue_chunk(c + 2, (c + 2) % 3);
            CP_COMMIT();
            CP_WAIT2();
        } else if (c + 1 < NCH) {
            CP_WAIT1();
        } else {
            CP_WAIT0();
        }
        __syncthreads();

        const uint32_t baseA = sb + (uint32_t)s * STAGE_BYTES;
        const uint32_t baseB = baseA + TILE_BYTES;

#pragma unroll
        for (int ks = 0; ks < 4; ks++) {
            const uint32_t kb = (uint32_t)(ks * 16 * 2);
            uint32_t bh[2][4];
#pragma unroll
            for (int p = 0; p < 2; p++) {
                uint32_t off = boff + (uint32_t)((n0 + p * 16) * ASTRIDE * 2) + kb;
                ldm_x4(bh[p][0], bh[p][1], bh[p][2], bh[p][3], baseB + off);
            }
#pragma unroll
            for (int tm = 0; tm < 4; tm++) {
                uint32_t off = aoff + (uint32_t)((m0 + tm * 16) * ASTRIDE * 2) + kb;
                uint32_t ah[4];
                ldm_x4(ah[0], ah[1], ah[2], ah[3], baseA + off);
#pragma unroll
                for (int tn = 0; tn < 4; tn++) {
                    int p = tn >> 1, q = tn & 1;
                    mma16816(acc[tm][tn], ah, bh[p][q * 2], bh[p][q * 2 + 1]);
                }
            }
        }
        __syncthreads();
    }

    const int rit = lane >> 2;
    const int cq = (lane & 3) * 2;
#pragma unroll
    for (int tm = 0; tm < 4; tm++) {
        float s1a = 0.f, s2a = 0.f, s1b = 0.f, s2b = 0.f;
#pragma unroll
        for (int tn = 0; tn < 4; tn++) {
            size_t row = (size_t)(bm + m0 + tm * 16 + rit);
            int col = bn + n0 + tn * 8 + cq;
            if (HALF_OUT) {
                __half2 v0 = __floats2half2_rn(acc[tm][tn][0], acc[tm][tn][1]);
                __half2 v1 = __floats2half2_rn(acc[tm][tn][2], acc[tm][tn][3]);
                *(__half2*)&Ch[row * CN + col] = v0;
                *(__half2*)&Ch[(row + 8) * CN + col] = v1;
            } else {
                *(float2*)&Cf[row * CN + col] = make_float2(acc[tm][tn][0], acc[tm][tn][1]);
                *(float2*)&Cf[(row + 8) * CN + col] = make_float2(acc[tm][tn][2], acc[tm][tn][3]);
            }
            if (DO_ATT) {
                float a0 = __ldg(att_s + col), a1 = __ldg(att_s + col + 1);
                float d0 = __ldg(att_d + col), d1 = __ldg(att_d + col + 1);
                s1a += acc[tm][tn][0] * a0 + acc[tm][tn][1] * a1;
                s2a += acc[tm][tn][0] * d0 + acc[tm][tn][1] * d1;
                s1b += acc[tm][tn][2] * a0 + acc[tm][tn][3] * a1;
                s2b += acc[tm][tn][2] * d0 + acc[tm][tn][3] * d1;
            }
        }
        if (DO_ATT) {
#pragma unroll
            for (int off = 1; off < 4; off <<= 1) {
                s1a += __shfl_xor_sync(0xffffffffu, s1a, off);
                s2a += __shfl_xor_sync(0xffffffffu, s2a, off);
                s1b += __shfl_xor_sync(0xffffffffu, s1b, off);
                s2b += __shfl_xor_sync(0xffffffffu, s2b, off);
            }
            if ((lane & 3) == 0) {
                int rowA = bm + m0 + tm * 16 + rit;
                atomicAdd(&g_asrc[rowA], s1a);
                atomicAdd(&g_adst[rowA], s2a);
                atomicAdd(&g_asrc[rowA + 8], s1b);
                atomicAdd(&g_adst[rowA + 8], s2b);
            }
        }
    }
}

__global__ void __launch_bounds__(256, 2) k_gemm1(const float* __restrict__ att_s,
                                                  const float* __restrict__ att_d) {
    mma_gemm_body<GATD, GATD, 12, true, true>(g_A1, g_W1, nullptr, g_hh, att_s, att_d);
}
__global__ void __launch_bounds__(256, 2) k_gemm2() {
    mma_gemm_body<PD, XDP, 13, false, false>(g_X, g_W2, g_P, nullptr, nullptr, nullptr);
}
#define GEMM_SMEM (3 * STAGE_BYTES)   // 110592

// ---------------- edge alpha pass (deg + amax) ----------------
__global__ void k_edge_alpha(const int* __restrict__ ei) {
    int e = blockIdx.x * blockDim.x + threadIdx.x;
    if (e >= NEDGE) return;
    int s = ei[e], d = ei[NEDGE + e];
    float al = lrelu(g_asrc[s] + g_adst[d]);
    g_alphaE[e] = al;
    atomicMax(&g_amax[d], f2o(al));
    atomicAdd(&g_deg[d], 1);
}

// ---- scan stage 1: per-block inclusive scan of deg + block sums; phase2 amax/denom ----
__global__ void k_scan1() {
    __shared__ int wsum[8];
    int t = threadIdx.x, lane = t & 31, wid = t >> 5;
    int i = blockIdx.x * 256 + t;
    int v = (i < NNODE) ? g_deg[i] : 0;
    int incl = v;
#pragma unroll
    for (int o = 1; o < 32; o <<= 1) {
        int n = __shfl_up_sync(0xffffffffu, incl, o);
        if (lane >= o) incl += n;
    }
    if (lane == 31) wsum[wid] = incl;
    __syncthreads();
    if (wid == 0 && lane < 8) {
        int w = wsum[lane];
        int ws = w;
#pragma unroll
        for (int o = 1; o < 8; o <<= 1) {
            int n = __shfl_up_sync(0xffu, ws, o);
            if (lane >= o) ws += n;
        }
        wsum[lane] = ws - w;   // exclusive across warps
    }
    __syncthreads();
    incl += wsum[wid];
    if (i < NNODE) g_rowstart[i] = incl;               // temp: block-local inclusive
    if (t == 255) g_bsum[blockIdx.x] = incl;
    // phase 2: amax includes self; denom = exp(self - amax)
    if (i < NNODE) {
        float al = lrelu(g_asrc[i] + g_adst[i]);
        float am = fmaxf(o2f(g_amax[i]), al);          // o2f(0)=NaN -> returns al
        g_amax[i] = f2o(am);
        g_denom[i] = __expf(al - am);
    }
}

// ---- scan stage 2: exclusive scan of 63 block sums (one warp, 2 elems/lane) ----
__global__ void k_scan2() {
    int lane = threadIdx.x;
    int v0 = (2 * lane     < SCAN_BLOCKS) ? g_bsum[2 * lane]     : 0;
    int v1 = (2 * lane + 1 < SCAN_BLOCKS) ? g_bsum[2 * lane + 1] : 0;
    int p = v0 + v1;
    int incl = p;
#pragma unroll
    for (int o = 1; o < 32; o <<= 1) {
        int n = __shfl_up_sync(0xffffffffu, incl, o);
        if (lane >= o) incl += n;
    }
    int excl = incl - p;
    if (2 * lane < SCAN_BLOCKS)     g_bofs[2 * lane] = excl;
    if (2 * lane + 1 < SCAN_BLOCKS) g_bofs[2 * lane + 1] = excl + v0;
}

// ---- scan stage 3: finalize rowstart/pos ----
__global__ void k_scan3() {
    int i = blockIdx.x * 256 + threadIdx.x;
    if (i >= NNODE) return;
    int excl = g_bofs[blockIdx.x] + g_rowstart[i] - g_deg[i];
    g_rowstart[i] = excl;
    g_pos[i] = excl;
}

// fused CSR fill + exp + denom accumulate
__global__ void k_edge_build(const int* __restrict__ ei) {
    int e = blockIdx.x * blockDim.x + threadIdx.x;
    if (e >= NEDGE) return;
    int s = ei[e], d = ei[NEDGE + e];
    int p = atomicAdd(&g_pos[d], 1);
    g_csr_src[p] = s;
    g_csr_eid[p] = e;
    float ex = __expf(g_alphaE[e] - o2f(g_amax[d]));
    g_csr_ex[p] = ex;
    atomicAdd(&g_denom[d], ex);
}

// ---------------- GAT gather-aggregation: warp per node (unroll-4 edges) ----------------
__global__ void k_gat_aggr(const float* __restrict__ b_gat) {
    int warp = (blockIdx.x * blockDim.x + threadIdx.x) >> 5;
    int lane = threadIdx.x & 31;
    if (warp >= NNODE) return;
    int i = warp;
    float amaxv = o2f(g_amax[i]);
    float als = lrelu(g_asrc[i] + g_adst[i]);
    float inv_den = 1.0f / g_denom[i];
    float cs = __expf(als - amaxv) * inv_den;

    const uint4* hrow = (const uint4*)(g_hh + (size_t)i * GATD);
    const float4* bg = (const float4*)b_gat;
    float acc[3][8];
#pragma unroll
    for (int t = 0; t < 3; t++) {
        float f[8];
        unpack8(hrow[lane + 32 * t], f);
        float4 b0 = bg[2 * (lane + 32 * t)];
        float4 b1 = bg[2 * (lane + 32 * t) + 1];
        acc[t][0] = cs * f[0] + b0.x; acc[t][1] = cs * f[1] + b0.y;
        acc[t][2] = cs * f[2] + b0.z; acc[t][3] = cs * f[3] + b0.w;
        acc[t][4] = cs * f[4] + b1.x; acc[t][5] = cs * f[5] + b1.y;
        acc[t][6] = cs * f[6] + b1.z; acc[t][7] = cs * f[7] + b1.w;
    }
    int rs = g_rowstart[i], d = g_deg[i];
    for (int base = 0; base < d; base += 32) {
        int cnt = min(32, d - base);
        int sj = 0;
        float cj = 0.f;
        if (lane < cnt) {
            sj = g_csr_src[rs + base + lane];
            cj = g_csr_ex[rs + base + lane] * inv_den;
        }
        int k = 0;
        for (; k + 3 < cnt; k += 4) {
            int ss[4];
            float cc[4];
#pragma unroll
            for (int u = 0; u < 4; u++) {
                ss[u] = __shfl_sync(0xffffffffu, sj, k + u);
                cc[u] = __shfl_sync(0xffffffffu, cj, k + u);
            }
            uint4 r[4][3];
#pragma unroll
            for (int u = 0; u < 4; u++) {
                const uint4* hp = (const uint4*)(g_hh + (size_t)ss[u] * GATD);
#pragma unroll
                for (int t = 0; t < 3; t++) r[u][t] = __ldg(&hp[lane + 32 * t]);
            }
#pragma unroll
            for (int u = 0; u < 4; u++)
#pragma unroll
                for (int t = 0; t < 3; t++) {
                    float f[8];
                    unpack8(r[u][t], f);
#pragma unroll
                    for (int q = 0; q < 8; q++) acc[t][q] += cc[u] * f[q];
                }
        }
        for (; k < cnt; k++) {
            int s0 = __shfl_sync(0xffffffffu, sj, k);
            float c0 = __shfl_sync(0xffffffffu, cj, k);
            const uint4* h0 = (const uint4*)(g_hh + (size_t)s0 * GATD);
#pragma unroll
            for (int t = 0; t < 3; t++) {
                float f0[8];
                unpack8(__ldg(&h0[lane + 32 * t]), f0);
#pragma unroll
                for (int q = 0; q < 8; q++) acc[t][q] += c0 * f0[q];
            }
        }
    }
    size_t xbase = (size_t)i * XDP;
#pragma unroll
    for (int t = 0; t < 3; t++) {
        *(uint4*)(g_X + xbase + 8 * (lane + 32 * t)) = pack8(acc[t]);
    }
}

// ---------------- final aggregation: per-lane ea accumulation + unroll-4 P2 gather ----------------
__global__ void k_meta(float* __restrict__ out, const float* __restrict__ b_nbr,
                       const float* __restrict__ b_self, const float* __restrict__ W_nbr,
                       const float* __restrict__ W_edge, const float* __restrict__ b_edge,
                       const float* __restrict__ edge_attr) {
    __shared__ float sWe[16 * 128];
    __shared__ float sWE[16 * 16];
    __shared__ float sBN[128];
    for (int t = threadIdx.x; t < 2048; t += blockDim.x)
        sWe[t] = W_nbr[1600 * 128 + t];
    for (int t = threadIdx.x; t < 256; t += blockDim.x)
        sWE[t] = W_edge[t];
    __syncthreads();
    if (threadIdx.x < 128) {
        int c = threadIdx.x;
        float s = b_nbr[c];
#pragma unroll
        for (int k = 0; k < 16; k++) s += b_edge[k] * sWe[k * 128 + c];
        sBN[c] = s;
    }
    __syncthreads();

    int warp = (blockIdx.x * blockDim.x + threadIdx.x) >> 5;
    int lane = threadIdx.x & 31;
    if (warp >= NNODE) return;
    int i = warp;
    const float4* Pr = (const float4*)(g_P + (size_t)i * PD);
    float4 p1 = Pr[lane];        // dst-part
    float4 xs = Pr[64 + lane];   // self-part
    float4 bs = ((const float4*)b_self)[lane];
    float4 bn4 = *(const float4*)&sBN[lane * 4];
    float degf = (float)g_deg[i];
    float4 acc;
    acc.x = xs.x + bs.x + degf * (p1.x + bn4.x);
    acc.y = xs.y + bs.y + degf * (p1.y + bn4.y);
    acc.z = xs.z + bs.z + degf * (p1.z + bn4.z);
    acc.w = xs.w + bs.w + degf * (p1.w + bn4.w);

    float eas[16];
#pragma unroll
    for (int k = 0; k < 16; k++) eas[k] = 0.f;

    int rs = g_rowstart[i], d = g_deg[i];
    for (int base = 0; base < d; base += 32) {
        int cnt = min(32, d - base);
        int sj = 0;
        if (lane < cnt) {
            sj = g_csr_src[rs + base + lane];
            int ej = g_csr_eid[rs + base + lane];
            const float4* ear = (const float4*)(edge_attr + (size_t)ej * 16);
            float4 e0 = __ldg(ear), e1 = __ldg(ear + 1), e2 = __ldg(ear + 2), e3 = __ldg(ear + 3);
            eas[0] += e0.x;  eas[1] += e0.y;  eas[2] += e0.z;  eas[3] += e0.w;
            eas[4] += e1.x;  eas[5] += e1.y;  eas[6] += e1.z;  eas[7] += e1.w;
            eas[8] += e2.x;  eas[9] += e2.y;  eas[10] += e2.z; eas[11] += e2.w;
            eas[12] += e3.x; eas[13] += e3.y; eas[14] += e3.z; eas[15] += e3.w;
        }
        int k = 0;
        for (; k + 3 < cnt; k += 4) {
            int ss[4];
#pragma unroll
            for (int u = 0; u < 4; u++) ss[u] = __shfl_sync(0xffffffffu, sj, k + u);
            float4 p2[4];
#pragma unroll
            for (int u = 0; u < 4; u++)
                p2[u] = __ldg(&((const float4*)(g_P + (size_t)ss[u] * PD))[32 + lane]);
#pragma unroll
            for (int u = 0; u < 4; u++) {
                acc.x += p2[u].x;
                acc.y += p2[u].y;
                acc.z += p2[u].z;
                acc.w += p2[u].w;
            }
        }
        for (; k < cnt; k++) {
            int s0 = __shfl_sync(0xffffffffu, sj, k);
            float4 p2 = __ldg(&((const float4*)(g_P + (size_t)s0 * PD))[32 + lane]);
            acc.x += p2.x;
            acc.y += p2.y;
            acc.z += p2.z;
            acc.w += p2.w;
        }
    }

    // reduce per-lane ea partials across the warp
#pragma unroll
    for (int o = 16; o > 0; o >>= 1)
#pragma unroll
        for (int kk = 0; kk < 16; kk++)
            eas[kk] += __shfl_xor_sync(0xffffffffu, eas[kk], o);

    float tv[16];
#pragma unroll
    for (int kk = 0; kk < 16; kk++) {
        float s = 0.f;
#pragma unroll
        for (int j = 0; j < 16; j++) s += eas[j] * sWE[j * 16 + kk];
        tv[kk] = s;
    }
    int col = lane * 4;
#pragma unroll
    for (int kk = 0; kk < 16; kk++) {
        float4 wv = *(const float4*)&sWe[kk * 128 + col];
        float ev = tv[kk];
        acc.x += ev * wv.x;
        acc.y += ev * wv.y;
        acc.z += ev * wv.z;
        acc.w += ev * wv.w;
    }
    ((float4*)(out + (size_t)i * MD))[lane] = acc;
}

// ---------------- launch ----------------
extern "C" void kernel_launch(void* const* d_in, const int* in_sizes, int n_in,
                              void* d_out, int out_size) {
    const float* node_feature    = (const float*)d_in[0];
    const float* edge_attr       = (const float*)d_in[1];
    const float* message_feature = (const float*)d_in[2];
    const int*   edge_index      = (const int*)d_in[3];
    const float* W_node = (const float*)d_in[4];
    const float* b_node = (const float*)d_in[5];
    const float* W_edge = (const float*)d_in[6];
    const float* b_edge = (const float*)d_in[7];
    const float* W_gat  = (const float*)d_in[8];
    const float* att_src = (const float*)d_in[9];
    const float* att_dst = (const float*)d_in[10];
    const float* b_gat  = (const float*)d_in[11];
    const float* W_nbr  = (const float*)d_in[12];
    const float* b_nbr  = (const float*)d_in[13];
    const float* W_self = (const float*)d_in[14];
    const float* b_self = (const float*)d_in[15];
    float* out = (float*)d_out;

    cudaFuncSetAttribute(k_gemm1, cudaFuncAttributeMaxDynamicSharedMemorySize, GEMM_SMEM);
    cudaFuncSetAttribute(k_gemm2, cudaFuncAttributeMaxDynamicSharedMemorySize, GEMM_SMEM);

    // fused prep (A1 convert | node learner | W2 | W1 transpose | zero init)
    k_prep<<<PREP_BLOCKS, 256>>>(message_feature, node_feature, W_node, b_node,
                                 W_gat, W_nbr, W_self);

    // h = mf @ W_gat  (fp16 out, + fused attention scalar partial dots)
    k_gemm1<<<dim3(GATD / 128, NNODE / 128), 256, GEMM_SMEM>>>(att_src, att_dst);

    // softmax structure (parallel 3-stage scan)
    k_edge_alpha<<<(NEDGE + 255) / 256, 256>>>(edge_index);
    k_scan1<<<SCAN_BLOCKS, 256>>>();
    k_scan2<<<1, 32>>>();
    k_scan3<<<SCAN_BLOCKS, 256>>>();
    k_edge_build<<<(NEDGE + 255) / 256, 256>>>(edge_index);

    // GAT aggregation -> X cols 0:768 (fp16 h rows)
    k_gat_aggr<<<(NNODE * 32 + 255) / 256, 256>>>(b_gat);

    // P = x @ Wcat  (fp16)
    k_gemm2<<<dim3(PD / 128, NNODE / 128), 256, GEMM_SMEM>>>();

    // final per-node aggregation (fused edge learner) -> out
    k_meta<<<(NNODE * 32 + 255) / 256, 256>>>(out, b_nbr, b_self, W_nbr,
                                              W_edge, b_edge, edge_attr);
}

// round 17
// speedup vs baseline: 1.5027x; 1.0113x over previous
#include <cuda_runtime.h>
#include <cuda_fp16.h>
#include <cstdint>

// ---------------- problem constants ----------------
#define NNODE 16000
#define NEDGE 128000
#define GATD 768          // GAT dim
#define XD 800            // meta-in dim (768 gat + 32 node)
#define XDP 832           // padded K for GEMM2 (13 x 64)
#define MD 128            // meta out dim
#define PD 384            // P1(dst part) | P2(src part) | Xself
#define SCAN_BLOCKS 63    // ceil(NNODE/256)

// ---------------- device scratch (no allocs allowed) ----------------
__device__ __half   g_hh[NNODE * GATD];      // h in fp16 (only consumer: gather)
__device__ float    g_P[NNODE * PD];         // 24.6 MB
__device__ float    g_asrc[NNODE];
__device__ float    g_adst[NNODE];
__device__ unsigned g_amax[NNODE];           // ordered-float bits (0 = -inf sentinel)
__device__ float    g_denom[NNODE];
__device__ float    g_alphaE[NEDGE];
__device__ int      g_deg[NNODE];
__device__ int      g_rowstart[NNODE];
__device__ int      g_pos[NNODE];
__device__ int      g_csr_src[NEDGE];
__device__ int      g_csr_eid[NEDGE];
__device__ float    g_csr_ex[NEDGE];
__device__ int      g_bsum[64];
// fp16 operands
__device__ __half g_A1[NNODE * GATD];
__device__ __half g_X[NNODE * XDP];
__device__ __half g_W1[GATD * GATD];   // W_gat^T  [n,k]
__device__ __half g_W2[PD * XDP];      // Wcat^T   [n,k]

// ---------------- helpers ----------------
__device__ __forceinline__ float lrelu(float x) { return x >= 0.f ? x : 0.2f * x; }
__device__ __forceinline__ unsigned f2o(float f) {
    unsigned b = __float_as_uint(f);
    return (b & 0x80000000u) ? ~b : (b | 0x80000000u);
}
__device__ __forceinline__ float o2f(unsigned b) {
    b = (b & 0x80000000u) ? (b & 0x7fffffffu) : ~b;
    return __uint_as_float(b);
}
__device__ __forceinline__ uint32_t smem_u32(const void* p) {
    uint32_t a;
    asm("{ .reg .u64 t; cvta.to.shared.u64 t, %1; cvt.u32.u64 %0, t; }" : "=r"(a) : "l"(p));
    return a;
}
__device__ __forceinline__ void ldm_x4(uint32_t& r0, uint32_t& r1, uint32_t& r2, uint32_t& r3,
                                       uint32_t addr) {
    asm volatile("ldmatrix.sync.aligned.m8n8.x4.shared.b16 {%0,%1,%2,%3}, [%4];"
                 : "=r"(r0), "=r"(r1), "=r"(r2), "=r"(r3) : "r"(addr));
}
__device__ __forceinline__ void mma16816(float* c, const uint32_t* a, uint32_t b0, uint32_t b1) {
    asm volatile(
        "mma.sync.aligned.m16n8k16.row.col.f32.f16.f16.f32 "
        "{%0,%1,%2,%3}, {%4,%5,%6,%7}, {%8,%9}, {%0,%1,%2,%3};"
        : "+f"(c[0]), "+f"(c[1]), "+f"(c[2]), "+f"(c[3])
        : "r"(a[0]), "r"(a[1]), "r"(a[2]), "r"(a[3]), "r"(b0), "r"(b1));
}
__device__ __forceinline__ void cp16(uint32_t dst, const void* src) {
    asm volatile("cp.async.cg.shared.global [%0], [%1], 16;" :: "r"(dst), "l"(src));
}
#define CP_COMMIT() asm volatile("cp.async.commit_group;" ::: "memory")
#define CP_WAIT1()  asm volatile("cp.async.wait_group 1;" ::: "memory")
#define CP_WAIT0()  asm volatile("cp.async.wait_group 0;" ::: "memory")

__device__ __forceinline__ void unpack8(uint4 v, float* f) {
    float2 a = __half22float2(*(__half2*)&v.x);
    float2 b = __half22float2(*(__half2*)&v.y);
    float2 c = __half22float2(*(__half2*)&v.z);
    float2 d = __half22float2(*(__half2*)&v.w);
    f[0] = a.x; f[1] = a.y; f[2] = b.x; f[3] = b.y;
    f[4] = c.x; f[5] = c.y; f[6] = d.x; f[7] = d.y;
}
__device__ __forceinline__ uint4 pack8(const float* f) {
    uint4 o;
    __half2 h0 = __floats2half2_rn(f[0], f[1]);
    __half2 h1 = __floats2half2_rn(f[2], f[3]);
    __half2 h2 = __floats2half2_rn(f[4], f[5]);
    __half2 h3 = __floats2half2_rn(f[6], f[7]);
    o.x = *(uint32_t*)&h0; o.y = *(uint32_t*)&h1;
    o.z = *(uint32_t*)&h2; o.w = *(uint32_t*)&h3;
    return o;
}

// ---------------- fused prep kernel (block-range dispatch) ----------------
#define PREP_B_A1  6000     // cvtA1: NNODE*GATD/4 float4, 2 per thread
#define PREP_B_NL  2000     // nodeL: NNODE*32 / 256
#define PREP_B_W2  1248     // cvtW2: PD*XDP / 256
#define PREP_B_W1  576      // cvtW1: (768/32)^2 tiles
#define PREP_B_Z   63       // zero init: ceil(16000/256)
#define PREP_BLOCKS (PREP_B_A1 + PREP_B_NL + PREP_B_W2 + PREP_B_W1 + PREP_B_Z)

__global__ void k_prep(const float* __restrict__ mf, const float* __restrict__ nf,
                       const float* __restrict__ Wnode, const float* __restrict__ bnode,
                       const float* __restrict__ Wg,
                       const float* __restrict__ Wnbr, const float* __restrict__ Wself) {
    __shared__ float tile[32][33];
    int b = blockIdx.x;
    int t = threadIdx.x;
    if (b < PREP_B_A1) {                       // A1 convert (2x float4 -> 2x half2x2)
        int idx0 = b * 512 + t;
#pragma unroll
        for (int u = 0; u < 2; u++) {
            int idx = idx0 + u * 256;
            float4 v = ((const float4*)mf)[idx];
            __half2 h0 = __floats2half2_rn(v.x, v.y);
            __half2 h1 = __floats2half2_rn(v.z, v.w);
            uint2 o;
            o.x = *(uint32_t*)&h0;
            o.y = *(uint32_t*)&h1;
            ((uint2*)g_A1)[idx] = o;
        }
        return;
    }
    b -= PREP_B_A1;
    if (b < PREP_B_NL) {                       // node learner -> X cols 768:832
        int idx = b * 256 + t;
        int i = idx >> 5, j = idx & 31;
        const float* r = nf + i * 32;
        float s = bnode[j];
#pragma unroll
        for (int k = 0; k < 32; k++) s += r[k] * Wnode[k * 32 + j];
        size_t base = (size_t)i * XDP;
        g_X[base + 768 + j] = __float2half_rn(s);
        g_X[base + 800 + j] = __float2half(0.f);
        return;
    }
    b -= PREP_B_NL;
    if (b < PREP_B_W2) {                       // W2 build
        int idx = b * 256 + t;
        int n = idx / XDP, k = idx % XDP;
        float v = 0.f;
        if (k < XD) {
            if (n < 128)      v = Wnbr[k * 128 + n];
            else if (n < 256) v = Wnbr[(800 + k) * 128 + (n - 128)];
            else              v = Wself[k * 128 + (n - 256)];
        }
        g_W2[idx] = __float2half_rn(v);
        return;
    }
    b -= PREP_B_W2;
    if (b < PREP_B_W1) {                       // W1 transpose (32x32 tile)
        int tx = t & 31, ty = t >> 5;          // 32 x 8
        int n0 = (b % 24) * 32, k0 = (b / 24) * 32;
#pragma unroll
        for (int i = 0; i < 4; i++)
            tile[ty + i * 8][tx] = Wg[(size_t)(k0 + ty + i * 8) * GATD + n0 + tx];
        __syncthreads();
#pragma unroll
        for (int i = 0; i < 4; i++) {
            size_t o = (size_t)(n0 + ty + i * 8) * GATD + k0 + tx;
            g_W1[o] = __float2half_rn(tile[tx][ty + i * 8]);
        }
        return;
    }
    b -= PREP_B_W1;
    {                                          // zero init
        int i = b * 256 + t;
        if (i < NNODE) {
            g_asrc[i] = 0.f;
            g_adst[i] = 0.f;
            g_amax[i] = 0u;    // below every ordered-float
            g_deg[i] = 0;
        }
    }
}

// ---------------- warp-MMA fp16 GEMM (cp.async 3-stage, K chunk 64, 1 barrier/chunk) ----------------
#define ASTRIDE 72
#define TILE_BYTES 18432                  // 128*72*2
#define STAGE_BYTES (2 * TILE_BYTES)      // A|B

template <int CN, int KPAD, int NCH, bool DO_ATT, bool HALF_OUT>
__device__ __forceinline__ void mma_gemm_body(const __half* __restrict__ A,
                                              const __half* __restrict__ B,
                                              float* __restrict__ Cf,
                                              __half* __restrict__ Ch,
                                              const float* __restrict__ att_s,
                                              const float* __restrict__ att_d) {
    extern __shared__ char smem[];
    const uint32_t sb = smem_u32(smem);

    const int t = threadIdx.x;
    const int lane = t & 31;
    const int wid = t >> 5;
    const int m0 = (wid >> 2) * 64;
    const int n0 = (wid & 3) * 32;
    const int bm = blockIdx.y * 128;
    const int bn = blockIdx.x * 128;

    const uint32_t aoff = (uint32_t)(((lane & 15) * ASTRIDE + (lane >> 4) * 8) * 2);
    const uint32_t boff = (uint32_t)((((lane & 7) + ((lane >> 4) << 3)) * ASTRIDE +
                                     (((lane >> 3) & 1) << 3)) * 2);

    float acc[4][4][4];
#pragma unroll
    for (int i = 0; i < 4; i++)
#pragma unroll
        for (int j = 0; j < 4; j++)
#pragma unroll
            for (int q = 0; q < 4; q++) acc[i][j][q] = 0.f;

    auto issue_chunk = [&](int c, int s) {
        const int c0 = c * 64;
        const uint32_t dst = sb + (uint32_t)s * STAGE_BYTES;
#pragma unroll
        for (int it = 0; it < 4; it++) {
            int idx = it * 256 + t;
            int r = idx >> 3, j = idx & 7;
            size_t ga = (size_t)(bm + r) * KPAD + c0 + j * 8;
            size_t gb = (size_t)(bn + r) * KPAD + c0 + j * 8;
            uint32_t doff = (uint32_t)((r * ASTRIDE + j * 8) * 2);
            cp16(dst + doff, A + ga);
            cp16(dst + TILE_BYTES + doff, B + gb);
        }
    };

    issue_chunk(0, 0);
    CP_COMMIT();
    issue_chunk(1, 1);
    CP_COMMIT();

    for (int c = 0; c < NCH; c++) {
        const int s = c % 3;
        // wait for chunk c's data (at most chunk c+1 may remain in flight)
        if (c + 1 < NCH) { CP_WAIT1(); } else { CP_WAIT0(); }
        __syncthreads();   // releases stage s for compute AND proves compute(c-1) done
        if (c + 2 < NCH) {
            issue_chunk(c + 2, (c + 2) % 3);   // stage (c+2)%3 == (c-1)%3, free now
            CP_COMMIT();
        }

        const uint32_t baseA = sb + (uint32_t)s * STAGE_BYTES;
        const uint32_t baseB = baseA + TILE_BYTES;

#pragma unroll
        for (int ks = 0; ks < 4; ks++) {
            const uint32_t kb = (uint32_t)(ks * 16 * 2);
            uint32_t bh[2][4];
#pragma unroll
            for (int p = 0; p < 2; p++) {
                uint32_t off = boff + (uint32_t)((n0 + p * 16) * ASTRIDE * 2) + kb;
                ldm_x4(bh[p][0], bh[p][1], bh[p][2], bh[p][3], baseB + off);
            }
#pragma unroll
            for (int tm = 0; tm < 4; tm++) {
                uint32_t off = aoff + (uint32_t)((m0 + tm * 16) * ASTRIDE * 2) + kb;
                uint32_t ah[4];
                ldm_x4(ah[0], ah[1], ah[2], ah[3], baseA + off);
#pragma unroll
                for (int tn = 0; tn < 4; tn++) {
                    int p = tn >> 1, q = tn & 1;
                    mma16816(acc[tm][tn], ah, bh[p][q * 2], bh[p][q * 2 + 1]);
                }
            }
        }
    }

    const int rit = lane >> 2;
    const int cq = (lane & 3) * 2;
#pragma unroll
    for (int tm = 0; tm < 4; tm++) {
        float s1a = 0.f, s2a = 0.f, s1b = 0.f, s2b = 0.f;
#pragma unroll
        for (int tn = 0; tn < 4; tn++) {
            size_t row = (size_t)(bm + m0 + tm * 16 + rit);
            int col = bn + n0 + tn * 8 + cq;
            if (HALF_OUT) {
                __half2 v0 = __floats2half2_rn(acc[tm][tn][0], acc[tm][tn][1]);
                __half2 v1 = __floats2half2_rn(acc[tm][tn][2], acc[tm][tn][3]);
                *(__half2*)&Ch[row * CN + col] = v0;
                *(__half2*)&Ch[(row + 8) * CN + col] = v1;
            } else {
                *(float2*)&Cf[row * CN + col] = make_float2(acc[tm][tn][0], acc[tm][tn][1]);
                *(float2*)&Cf[(row + 8) * CN + col] = make_float2(acc[tm][tn][2], acc[tm][tn][3]);
            }
            if (DO_ATT) {
                float a0 = __ldg(att_s + col), a1 = __ldg(att_s + col + 1);
                float d0 = __ldg(att_d + col), d1 = __ldg(att_d + col + 1);
                s1a += acc[tm][tn][0] * a0 + acc[tm][tn][1] * a1;
                s2a += acc[tm][tn][0] * d0 + acc[tm][tn][1] * d1;
                s1b += acc[tm][tn][2] * a0 + acc[tm][tn][3] * a1;
                s2b += acc[tm][tn][2] * d0 + acc[tm][tn][3] * d1;
            }
        }
        if (DO_ATT) {
#pragma unroll
            for (int off = 1; off < 4; off <<= 1) {
                s1a += __shfl_xor_sync(0xffffffffu, s1a, off);
                s2a += __shfl_xor_sync(0xffffffffu, s2a, off);
                s1b += __shfl_xor_sync(0xffffffffu, s1b, off);
                s2b += __shfl_xor_sync(0xffffffffu, s2b, off);
            }
            if ((lane & 3) == 0) {
                int rowA = bm + m0 + tm * 16 + rit;
                atomicAdd(&g_asrc[rowA], s1a);
                atomicAdd(&g_adst[rowA], s2a);
                atomicAdd(&g_asrc[rowA + 8], s1b);
                atomicAdd(&g_adst[rowA + 8], s2b);
            }
        }
    }
}

__global__ void __launch_bounds__(256, 2) k_gemm1(const float* __restrict__ att_s,
                                                  const float* __restrict__ att_d) {
    mma_gemm_body<GATD, GATD, 12, true, true>(g_A1, g_W1, nullptr, g_hh, att_s, att_d);
}
__global__ void __launch_bounds__(256, 2) k_gemm2() {
    mma_gemm_body<PD, XDP, 13, false, false>(g_X, g_W2, g_P, nullptr, nullptr, nullptr);
}
#define GEMM_SMEM (3 * STAGE_BYTES)   // 110592

// ---------------- edge alpha pass (deg + amax), 2 edges/thread ----------------
__global__ void k_edge_alpha(const int* __restrict__ ei) {
    int p = blockIdx.x * blockDim.x + threadIdx.x;
    if (p >= NEDGE / 2) return;
    int2 ss = ((const int2*)ei)[p];
    int2 dd = ((const int2*)(ei + NEDGE))[p];
    float al0 = lrelu(g_asrc[ss.x] + g_adst[dd.x]);
    float al1 = lrelu(g_asrc[ss.y] + g_adst[dd.y]);
    ((float2*)g_alphaE)[p] = make_float2(al0, al1);
    atomicMax(&g_amax[dd.x], f2o(al0));
    atomicMax(&g_amax[dd.y], f2o(al1));
    atomicAdd(&g_deg[dd.x], 1);
    atomicAdd(&g_deg[dd.y], 1);
}

// ---- scan stage 1: per-block inclusive scan of deg + block sums; phase2 amax/denom ----
__global__ void k_scan1() {
    __shared__ int wsum[8];
    int t = threadIdx.x, lane = t & 31, wid = t >> 5;
    int i = blockIdx.x * 256 + t;
    int v = (i < NNODE) ? g_deg[i] : 0;
    int incl = v;
#pragma unroll
    for (int o = 1; o < 32; o <<= 1) {
        int n = __shfl_up_sync(0xffffffffu, incl, o);
        if (lane >= o) incl += n;
    }
    if (lane == 31) wsum[wid] = incl;
    __syncthreads();
    if (wid == 0 && lane < 8) {
        int w = wsum[lane];
        int ws = w;
#pragma unroll
        for (int o = 1; o < 8; o <<= 1) {
            int n = __shfl_up_sync(0xffu, ws, o);
            if (lane >= o) ws += n;
        }
        wsum[lane] = ws - w;   // exclusive across warps
    }
    __syncthreads();
    incl += wsum[wid];
    if (i < NNODE) g_rowstart[i] = incl;               // temp: block-local inclusive
    if (t == 255) g_bsum[blockIdx.x] = incl;
    // phase 2: amax includes self; denom = exp(self - amax)
    if (i < NNODE) {
        float al = lrelu(g_asrc[i] + g_adst[i]);
        float am = fmaxf(o2f(g_amax[i]), al);          // o2f(0)=NaN -> returns al
        g_amax[i] = f2o(am);
        g_denom[i] = __expf(al - am);
    }
}

// ---- scan stage 3: finalize rowstart/pos (computes own block offset locally) ----
__global__ void k_scan3() {
    __shared__ int s_bofs;
    int t = threadIdx.x;
    if (t < 32) {
        int v = 0;
        if (t < blockIdx.x) v += g_bsum[t];
        if (t + 32 < blockIdx.x) v += g_bsum[t + 32];
#pragma unroll
        for (int o = 16; o > 0; o >>= 1) v += __shfl_xor_sync(0xffffffffu, v, o);
        if (t == 0) s_bofs = v;
    }
    __syncthreads();
    int i = blockIdx.x * 256 + t;
    if (i >= NNODE) return;
    int excl = s_bofs + g_rowstart[i] - g_deg[i];
    g_rowstart[i] = excl;
    g_pos[i] = excl;
}

// fused CSR fill + exp + denom accumulate, 2 edges/thread
__global__ void k_edge_build(const int* __restrict__ ei) {
    int pp = blockIdx.x * blockDim.x + threadIdx.x;
    if (pp >= NEDGE / 2) return;
    int2 ss = ((const int2*)ei)[pp];
    int2 dd = ((const int2*)(ei + NEDGE))[pp];
    float2 al = ((const float2*)g_alphaE)[pp];
    int e0 = 2 * pp, e1 = 2 * pp + 1;
    {
        int p = atomicAdd(&g_pos[dd.x], 1);
        g_csr_src[p] = ss.x;
        g_csr_eid[p] = e0;
        float ex = __expf(al.x - o2f(g_amax[dd.x]));
        g_csr_ex[p] = ex;
        atomicAdd(&g_denom[dd.x], ex);
    }
    {
        int p = atomicAdd(&g_pos[dd.y], 1);
        g_csr_src[p] = ss.y;
        g_csr_eid[p] = e1;
        float ex = __expf(al.y - o2f(g_amax[dd.y]));
        g_csr_ex[p] = ex;
        atomicAdd(&g_denom[dd.y], ex);
    }
}

// ---------------- GAT gather-aggregation: warp per node (unroll-4 edges) ----------------
__global__ void k_gat_aggr(const float* __restrict__ b_gat) {
    int warp = (blockIdx.x * blockDim.x + threadIdx.x) >> 5;
    int lane = threadIdx.x & 31;
    if (warp >= NNODE) return;
    int i = warp;
    float amaxv = o2f(g_amax[i]);
    float als = lrelu(g_asrc[i] + g_adst[i]);
    float inv_den = 1.0f / g_denom[i];
    float cs = __expf(als - amaxv) * inv_den;

    const uint4* hrow = (const uint4*)(g_hh + (size_t)i * GATD);
    const float4* bg = (const float4*)b_gat;
    float acc[3][8];
#pragma unroll
    for (int t = 0; t < 3; t++) {
        float f[8];
        unpack8(hrow[lane + 32 * t], f);
        float4 b0 = bg[2 * (lane + 32 * t)];
        float4 b1 = bg[2 * (lane + 32 * t) + 1];
        acc[t][0] = cs * f[0] + b0.x; acc[t][1] = cs * f[1] + b0.y;
        acc[t][2] = cs * f[2] + b0.z; acc[t][3] = cs * f[3] + b0.w;
        acc[t][4] = cs * f[4] + b1.x; acc[t][5] = cs * f[5] + b1.y;
        acc[t][6] = cs * f[6] + b1.z; acc[t][7] = cs * f[7] + b1.w;
    }
    int rs = g_rowstart[i], d = g_deg[i];
    for (int base = 0; base < d; base += 32) {
        int cnt = min(32, d - base);
        int sj = 0;
        float cj = 0.f;
        if (lane < cnt) {
            sj = g_csr_src[rs + base + lane];
            cj = g_csr_ex[rs + base + lane] * inv_den;
        }
        int k = 0;
        for (; k + 3 < cnt; k += 4) {
            int ss[4];
            float cc[4];
#pragma unroll
            for (int u = 0; u < 4; u++) {
                ss[u] = __shfl_sync(0xffffffffu, sj, k + u);
                cc[u] = __shfl_sync(0xffffffffu, cj, k + u);
            }
            uint4 r[4][3];
#pragma unroll
            for (int u = 0; u < 4; u++) {
                const uint4* hp = (const uint4*)(g_hh + (size_t)ss[u] * GATD);
#pragma unroll
                for (int t = 0; t < 3; t++) r[u][t] = __ldg(&hp[lane + 32 * t]);
            }
#pragma unroll
            for (int u = 0; u < 4; u++)
#pragma unroll
                for (int t = 0; t < 3; t++) {
                    float f[8];
                    unpack8(r[u][t], f);
#pragma unroll
                    for (int q = 0; q < 8; q++) acc[t][q] += cc[u] * f[q];
                }
        }
        for (; k < cnt; k++) {
            int s0 = __shfl_sync(0xffffffffu, sj, k);
            float c0 = __shfl_sync(0xffffffffu, cj, k);
            const uint4* h0 = (const uint4*)(g_hh + (size_t)s0 * GATD);
#pragma unroll
            for (int t = 0; t < 3; t++) {
                float f0[8];
                unpack8(__ldg(&h0[lane + 32 * t]), f0);
#pragma unroll
                for (int q = 0; q < 8; q++) acc[t][q] += c0 * f0[q];
            }
        }
    }
    size_t xbase = (size_t)i * XDP;
#pragma unroll
    for (int t = 0; t < 3; t++) {
        *(uint4*)(g_X + xbase + 8 * (lane + 32 * t)) = pack8(acc[t]);
    }
}

// ---------------- final aggregation: per-lane ea accumulation + unroll-4 P2 gather ----------------
__global__ void k_meta(float* __restrict__ out, const float* __restrict__ b_nbr,
                       const float* __restrict__ b_self, const float* __restrict__ W_nbr,
                       const float* __restrict__ W_edge, const float* __restrict__ b_edge,
                       const float* __restrict__ edge_attr) {
    __shared__ float sWe[16 * 128];
    __shared__ float sWE[16 * 16];
    __shared__ float sBN[128];
    for (int t = threadIdx.x; t < 2048; t += blockDim.x)
        sWe[t] = W_nbr[1600 * 128 + t];
    for (int t = threadIdx.x; t < 256; t += blockDim.x)
        sWE[t] = W_edge[t];
    __syncthreads();
    if (threadIdx.x < 128) {
        int c = threadIdx.x;
        float s = b_nbr[c];
#pragma unroll
        for (int k = 0; k < 16; k++) s += b_edge[k] * sWe[k * 128 + c];
        sBN[c] = s;
    }
    __syncthreads();

    int warp = (blockIdx.x * blockDim.x + threadIdx.x) >> 5;
    int lane = threadIdx.x & 31;
    if (warp >= NNODE) return;
    int i = warp;
    const float4* Pr = (const float4*)(g_P + (size_t)i * PD);
    float4 p1 = Pr[lane];        // dst-part
    float4 xs = Pr[64 + lane];   // self-part
    float4 bs = ((const float4*)b_self)[lane];
    float4 bn4 = *(const float4*)&sBN[lane * 4];
    float degf = (float)g_deg[i];
    float4 acc;
    acc.x = xs.x + bs.x + degf * (p1.x + bn4.x);
    acc.y = xs.y + bs.y + degf * (p1.y + bn4.y);
    acc.z = xs.z + bs.z + degf * (p1.z + bn4.z);
    acc.w = xs.w + bs.w + degf * (p1.w + bn4.w);

    float eas[16];
#pragma unroll
    for (int k = 0; k < 16; k++) eas[k] = 0.f;

    int rs = g_rowstart[i], d = g_deg[i];
    for (int base = 0; base < d; base += 32) {
        int cnt = min(32, d - base);
        int sj = 0;
        if (lane < cnt) {
            sj = g_csr_src[rs + base + lane];
            int ej = g_csr_eid[rs + base + lane];
            const float4* ear = (const float4*)(edge_attr + (size_t)ej * 16);
            float4 e0 = __ldg(ear), e1 = __ldg(ear + 1), e2 = __ldg(ear + 2), e3 = __ldg(ear + 3);
            eas[0] += e0.x;  eas[1] += e0.y;  eas[2] += e0.z;  eas[3] += e0.w;
            eas[4] += e1.x;  eas[5] += e1.y;  eas[6] += e1.z;  eas[7] += e1.w;
            eas[8] += e2.x;  eas[9] += e2.y;  eas[10] += e2.z; eas[11] += e2.w;
            eas[12] += e3.x; eas[13] += e3.y; eas[14] += e3.z; eas[15] += e3.w;
        }
        int k = 0;
        for (; k + 3 < cnt; k += 4) {
            int ss[4];
#pragma unroll
            for (int u = 0; u < 4; u++) ss[u] = __shfl_sync(0xffffffffu, sj, k + u);
            float4 p2[4];
#pragma unroll
            for (int u = 0; u < 4; u++)
                p2[u] = __ldg(&((const float4*)(g_P + (size_t)ss[u] * PD))[32 + lane]);
#pragma unroll
            for (int u = 0; u < 4; u++) {
                acc.x += p2[u].x;
                acc.y += p2[u].y;
                acc.z += p2[u].z;
                acc.w += p2[u].w;
            }
        }
        for (; k < cnt; k++) {
            int s0 = __shfl_sync(0xffffffffu, sj, k);
            float4 p2 = __ldg(&((const float4*)(g_P + (size_t)s0 * PD))[32 + lane]);
            acc.x += p2.x;
            acc.y += p2.y;
            acc.z += p2.z;
            acc.w += p2.w;
        }
    }

    // reduce per-lane ea partials across the warp
#pragma unroll
    for (int o = 16; o > 0; o >>= 1)
#pragma unroll
        for (int kk = 0; kk < 16; kk++)
            eas[kk] += __shfl_xor_sync(0xffffffffu, eas[kk], o);

    float tv[16];
#pragma unroll
    for (int kk = 0; kk < 16; kk++) {
        float s = 0.f;
#pragma unroll
        for (int j = 0; j < 16; j++) s += eas[j] * sWE[j * 16 + kk];
        tv[kk] = s;
    }
    int col = lane * 4;
#pragma unroll
    for (int kk = 0; kk < 16; kk++) {
        float4 wv = *(const float4*)&sWe[kk * 128 + col];
        float ev = tv[kk];
        acc.x += ev * wv.x;
        acc.y += ev * wv.y;
        acc.z += ev * wv.z;
        acc.w += ev * wv.w;
    }
    ((float4*)(out + (size_t)i * MD))[lane] = acc;
}

// ---------------- launch ----------------
extern "C" void kernel_launch(void* const* d_in, const int* in_sizes, int n_in,
                              void* d_out, int out_size) {
    const float* node_feature    = (const float*)d_in[0];
    const float* edge_attr       = (const float*)d_in[1];
    const float* message_feature = (const float*)d_in[2];
    const int*   edge_index      = (const int*)d_in[3];
    const float* W_node = (const float*)d_in[4];
    const float* b_node = (const float*)d_in[5];
    const float* W_edge = (const float*)d_in[6];
    const float* b_edge = (const float*)d_in[7];
    const float* W_gat  = (const float*)d_in[8];
    const float* att_src = (const float*)d_in[9];
    const float* att_dst = (const float*)d_in[10];
    const float* b_gat  = (const float*)d_in[11];
    const float* W_nbr  = (const float*)d_in[12];
    const float* b_nbr  = (const float*)d_in[13];
    const float* W_self = (const float*)d_in[14];
    const float* b_self = (const float*)d_in[15];
    float* out = (float*)d_out;

    cudaFuncSetAttribute(k_gemm1, cudaFuncAttributeMaxDynamicSharedMemorySize, GEMM_SMEM);
    cudaFuncSetAttribute(k_gemm2, cudaFuncAttributeMaxDynamicSharedMemorySize, GEMM_SMEM);

    // fused prep (A1 convert | node learner | W2 | W1 transpose | zero init)
    k_prep<<<PREP_BLOCKS, 256>>>(message_feature, node_feature, W_node, b_node,
                                 W_gat, W_nbr, W_self);

    // h = mf @ W_gat  (fp16 out, + fused attention scalar partial dots)
    k_gemm1<<<dim3(GATD / 128, NNODE / 128), 256, GEMM_SMEM>>>(att_src, att_dst);

    // softmax structure (parallel scan, scan2 folded into scan3)
    k_edge_alpha<<<(NEDGE / 2 + 255) / 256, 256>>>(edge_index);
    k_scan1<<<SCAN_BLOCKS, 256>>>();
    k_scan3<<<SCAN_BLOCKS, 256>>>();
    k_edge_build<<<(NEDGE / 2 + 255) / 256, 256>>>(edge_index);

    // GAT aggregation -> X cols 0:768 (fp16 h rows)
    k_gat_aggr<<<(NNODE * 32 + 255) / 256, 256>>>(b_gat);

    // P = x @ Wcat  (fp16)
    k_gemm2<<<dim3(PD / 128, NNODE / 128), 256, GEMM_SMEM>>>();

    // final per-node aggregation (fused edge learner) -> out
    k_meta<<<(NNODE * 32 + 255) / 256, 256>>>(out, b_nbr, b_self, W_nbr,
                                              W_edge, b_edge, edge_attr);
}